// round 7
// baseline (speedup 1.0000x reference)
#include <cuda_runtime.h>
#include <cstdint>

// ---------------------------------------------------------------------------
// EdgeDecoder: per-edge 3-layer MLP over gathered node-pair embeddings.
//
// Factorization: h1 = relu(emb[src]@W1a + emb[dst]@W1b + b1)
//   -> precompute A[n] = emb[n]@W1a, B[n] = emb[n]@W1b + b1 per node.
// Per-edge work drops from 4128 to ~2100 MACs; layer 2 runs on packed
// fma.rn.f32x2 (2 FMA/instr) with k-contiguous transposed W2 in SMEM.
// ---------------------------------------------------------------------------

#define MAX_NODES 100000
#define EDGE_USE_F32X2 1   // set 0 to fall back to scalar FFMA if toolchain balks

// Scratch (static __device__ globals: allocation-free per harness rules)
__device__ float g_A[MAX_NODES * 64];     // 25.6 MB
__device__ float g_B[MAX_NODES * 64];     // 25.6 MB
__device__ float g_W2T[32 * 64];          // W2 transposed: [j][k], k contiguous

// ---- f32x2 helpers --------------------------------------------------------
__device__ __forceinline__ unsigned long long pack2(float lo, float hi) {
    unsigned long long r;
    asm("mov.b64 %0, {%1, %2};" : "=l"(r) : "f"(lo), "f"(hi));
    return r;
}
__device__ __forceinline__ float2 unpack2(unsigned long long v) {
    float lo, hi;
    asm("mov.b64 {%0, %1}, %2;" : "=f"(lo), "=f"(hi) : "l"(v));
    return make_float2(lo, hi);
}
#if EDGE_USE_F32X2
__device__ __forceinline__ unsigned long long fma2(unsigned long long a,
                                                   unsigned long long b,
                                                   unsigned long long c) {
    unsigned long long d;
    asm("fma.rn.f32x2 %0, %1, %2, %3;" : "=l"(d) : "l"(a), "l"(b), "l"(c));
    return d;
}
__device__ __forceinline__ unsigned long long add2(unsigned long long a,
                                                   unsigned long long b) {
    unsigned long long d;
    asm("add.rn.f32x2 %0, %1, %2;" : "=l"(d) : "l"(a), "l"(b));
    return d;
}
#else
__device__ __forceinline__ unsigned long long fma2(unsigned long long a,
                                                   unsigned long long b,
                                                   unsigned long long c) {
    float2 af = unpack2(a), bf = unpack2(b), cf = unpack2(c);
    return pack2(fmaf(af.x, bf.x, cf.x), fmaf(af.y, bf.y, cf.y));
}
__device__ __forceinline__ unsigned long long add2(unsigned long long a,
                                                   unsigned long long b) {
    float2 af = unpack2(a), bf = unpack2(b);
    return pack2(af.x + bf.x, af.y + bf.y);
}
#endif

// ---- prep: transpose W2 (64x32 row-major) -> W2T (32 rows of 64 k-vals) ---
__global__ void prep_w2(const float* __restrict__ W2) {
    int i = blockIdx.x * blockDim.x + threadIdx.x;
    if (i < 64 * 32) {
        int k = i >> 5;       // 0..63
        int j = i & 31;       // 0..31
        g_W2T[j * 64 + k] = W2[i];
    }
}

// ---- prep: per-node A = emb@W1a, B = emb@W1b + b1 -------------------------
__global__ void prep_ab(const float* __restrict__ emb,
                        const float* __restrict__ W1,
                        const float* __restrict__ b1,
                        int n_nodes) {
    __shared__ float sW1[32 * 64];
    __shared__ float sb1[64];
    for (int i = threadIdx.x; i < 32 * 64; i += blockDim.x) sW1[i] = W1[i];
    for (int i = threadIdx.x; i < 64; i += blockDim.x)      sb1[i] = b1[i];
    __syncthreads();

    int n = blockIdx.x * blockDim.x + threadIdx.x;
    if (n >= n_nodes) return;

    float e[16];
    const float4* e4 = reinterpret_cast<const float4*>(emb + (size_t)n * 16);
#pragma unroll
    for (int i = 0; i < 4; i++) {
        float4 v = e4[i];
        e[4 * i + 0] = v.x; e[4 * i + 1] = v.y;
        e[4 * i + 2] = v.z; e[4 * i + 3] = v.w;
    }

    float* Arow = g_A + (size_t)n * 64;
    float* Brow = g_B + (size_t)n * 64;
#pragma unroll 4
    for (int j = 0; j < 64; j++) {
        float a = 0.f, b = 0.f;
#pragma unroll
        for (int k = 0; k < 16; k++) {
            a = fmaf(e[k], sW1[k * 64 + j], a);
            b = fmaf(e[k], sW1[(16 + k) * 64 + j], b);
        }
        Arow[j] = a;
        Brow[j] = b + sb1[j];
    }
}

// ---- main: per-edge MLP ---------------------------------------------------
__global__ __launch_bounds__(256, 3)
void edge_mlp(const int* __restrict__ ei,
              const float* __restrict__ b2,
              const float* __restrict__ W3,
              const float* __restrict__ b3,
              float* __restrict__ out,
              int E) {
    // W2T staged as 16B vectors: sW2[j*16 + q] covers k = 4q..4q+3 of column j
    __shared__ ulonglong2 sW2[32 * 16];
    __shared__ float sb2[32];
    __shared__ float sW3[32];
    __shared__ float sb3s;

    {
        float4* dst = reinterpret_cast<float4*>(sW2);
        const float4* src = reinterpret_cast<const float4*>(g_W2T);
        for (int i = threadIdx.x; i < 512; i += blockDim.x) dst[i] = src[i];
        if (threadIdx.x < 32) {
            sb2[threadIdx.x] = b2[threadIdx.x];
            sW3[threadIdx.x] = W3[threadIdx.x];
        }
        if (threadIdx.x == 0) sb3s = b3[0];
    }
    __syncthreads();

    int e = blockIdx.x * blockDim.x + threadIdx.x;
    if (e >= E) return;

    int src_n = ei[e];
    int dst_n = ei[E + e];

    const float4* a4 = reinterpret_cast<const float4*>(g_A) + (size_t)src_n * 16;
    const float4* b4 = reinterpret_cast<const float4*>(g_B) + (size_t)dst_n * 16;

    // h1[32] f32x2 regs = relu(A[src] + B[dst])   (b1 folded into B)
    unsigned long long h1[32];
#pragma unroll
    for (int i = 0; i < 16; i++) {
        float4 av = __ldg(a4 + i);
        float4 bv = __ldg(b4 + i);
        h1[2 * i]     = pack2(fmaxf(av.x + bv.x, 0.f), fmaxf(av.y + bv.y, 0.f));
        h1[2 * i + 1] = pack2(fmaxf(av.z + bv.z, 0.f), fmaxf(av.w + bv.w, 0.f));
    }

    float oacc = sb3s;

    // layer 2 + fused layer 3: 2 output columns per iter, 4 fma2 chains
#pragma unroll 1
    for (int j = 0; j < 32; j += 2) {
        unsigned long long acc0 = 0ull, acc1 = 0ull, acc2 = 0ull, acc3 = 0ull;
        const ulonglong2* w0 = &sW2[(j + 0) * 16];
        const ulonglong2* w1 = &sW2[(j + 1) * 16];
#pragma unroll
        for (int q = 0; q < 16; q += 2) {
            ulonglong2 wa = w0[q];
            ulonglong2 wb = w0[q + 1];
            acc0 = fma2(h1[2 * q + 0], wa.x, acc0);
            acc1 = fma2(h1[2 * q + 1], wa.y, acc1);
            acc0 = fma2(h1[2 * q + 2], wb.x, acc0);
            acc1 = fma2(h1[2 * q + 3], wb.y, acc1);
            ulonglong2 wc = w1[q];
            ulonglong2 wd = w1[q + 1];
            acc2 = fma2(h1[2 * q + 0], wc.x, acc2);
            acc3 = fma2(h1[2 * q + 1], wc.y, acc3);
            acc2 = fma2(h1[2 * q + 2], wd.x, acc2);
            acc3 = fma2(h1[2 * q + 3], wd.y, acc3);
        }
        float2 s0 = unpack2(add2(acc0, acc1));
        float2 s1 = unpack2(add2(acc2, acc3));
        float h2a = fmaxf(s0.x + s0.y + sb2[j + 0], 0.f);
        float h2b = fmaxf(s1.x + s1.y + sb2[j + 1], 0.f);
        oacc = fmaf(h2a, sW3[j + 0], oacc);
        oacc = fmaf(h2b, sW3[j + 1], oacc);
    }

    // sigmoid (fast-math: MUFU-based exp + rcp; tolerance is 1e-3)
    out[e] = __fdividef(1.0f, 1.0f + __expf(-oacc));
}

// ---- optional second output: edge_index cast to output dtype --------------
__global__ void idx_to_float(const int* __restrict__ ei, float* __restrict__ out, int n) {
    int i = blockIdx.x * blockDim.x + threadIdx.x;
    if (i < n) out[i] = (float)ei[i];
}

// ---------------------------------------------------------------------------
extern "C" void kernel_launch(void* const* d_in, const int* in_sizes, int n_in,
                              void* d_out, int out_size) {
    const float* emb = (const float*)d_in[0];   // [N_NODES, 16]
    const int*   ei  = (const int*)  d_in[1];   // [2, E]
    const float* W1  = (const float*)d_in[2];   // [32, 64]
    const float* b1  = (const float*)d_in[3];   // [64]
    const float* W2  = (const float*)d_in[4];   // [64, 32]
    const float* b2  = (const float*)d_in[5];   // [32]
    const float* W3  = (const float*)d_in[6];   // [32, 1]
    const float* b3  = (const float*)d_in[7];   // [1]

    int n_nodes = in_sizes[0] / 16;
    int E       = in_sizes[1] / 2;
    float* out  = (float*)d_out;

    prep_w2<<<(64 * 32 + 255) / 256, 256>>>(W2);
    prep_ab<<<(n_nodes + 127) / 128, 128>>>(emb, W1, b1, n_nodes);
    edge_mlp<<<(E + 255) / 256, 256>>>(ei, b2, W3, b3, out, E);

    // Reference returns (edge_probs, edge_index); if the harness flattened
    // both outputs into d_out, append edge_index value-cast to float.
    if (out_size >= 3 * E) {
        idx_to_float<<<(2 * E + 255) / 256, 256>>>(ei, out + E, 2 * E);
    }
}